// round 1
// baseline (speedup 1.0000x reference)
#include <cuda_runtime.h>

#define HW 192
#define F 100

// Ping-pong activation buffers: 2 * 100 * 192 * 192 floats = 29.5 MB each.
__device__ float g_buf0[2 * F * HW * HW];
__device__ float g_buf1[2 * F * HW * HW];

// ---------------------------------------------------------------------------
// conv 5x5, stride 1, SAME padding, + bias + relu.
// Block: 256 threads -> 32x32 spatial tile, 10 output channels.
// Each thread: 2x2 pixels x 10 couts = 40 accumulators.
// ---------------------------------------------------------------------------
template <int CIN, int CCH>
__global__ __launch_bounds__(256)
void conv5_relu(const float* __restrict__ in, const float* __restrict__ w,
                const float* __restrict__ bias, float* __restrict__ out) {
    __shared__ float s_in[CCH][36][37];   // odd pitch -> conflict-free strided reads
    __shared__ float s_w[CCH][25][10];    // broadcast reads over cout

    const int t = threadIdx.x;
    const int tx = t & 15, ty = t >> 4;
    const int tileX = (blockIdx.x % 6) * 32;
    const int tileY = (blockIdx.x / 6) * 32;
    const int co0 = blockIdx.y * 10;
    const int b = blockIdx.z;
    const float* inb = in + (size_t)b * CIN * (HW * HW);

    float acc[10][4];
#pragma unroll
    for (int c = 0; c < 10; c++)
#pragma unroll
        for (int p = 0; p < 4; p++) acc[c][p] = 0.f;

    for (int ci0 = 0; ci0 < CIN; ci0 += CCH) {
        __syncthreads();
        // stage input patch (36x36 per cin, zero-padded at borders)
        for (int i = t; i < CCH * 36 * 36; i += 256) {
            int cc = i / (36 * 36);
            int rem = i - cc * (36 * 36);
            int r = rem / 36, c = rem - r * 36;
            int gy = tileY + r - 2, gx = tileX + c - 2;
            float v = 0.f;
            if ((unsigned)gy < HW && (unsigned)gx < HW)
                v = inb[(size_t)(ci0 + cc) * (HW * HW) + gy * HW + gx];
            s_in[cc][r][c] = v;
        }
        // stage weights: global layout w[cout][cin][ky][kx]
        for (int i = t; i < CCH * 250; i += 256) {
            int co = i % 10;
            int tap = (i / 10) % 25;
            int cc = i / 250;
            s_w[cc][tap][co] = w[((size_t)(co0 + co) * CIN + (ci0 + cc)) * 25 + tap];
        }
        __syncthreads();

#pragma unroll 1
        for (int cc = 0; cc < CCH; cc++) {
#pragma unroll 1
            for (int ky = 0; ky < 5; ky++) {
                const int r0 = 2 * ty + ky;
#pragma unroll
                for (int kx = 0; kx < 5; kx++) {
                    const int c0 = 2 * tx + kx;
                    float x00 = s_in[cc][r0][c0];
                    float x01 = s_in[cc][r0][c0 + 1];
                    float x10 = s_in[cc][r0 + 1][c0];
                    float x11 = s_in[cc][r0 + 1][c0 + 1];
                    const int tap = ky * 5 + kx;
#pragma unroll
                    for (int co = 0; co < 10; co++) {
                        float wv = s_w[cc][tap][co];
                        acc[co][0] = fmaf(wv, x00, acc[co][0]);
                        acc[co][1] = fmaf(wv, x01, acc[co][1]);
                        acc[co][2] = fmaf(wv, x10, acc[co][2]);
                        acc[co][3] = fmaf(wv, x11, acc[co][3]);
                    }
                }
            }
        }
    }

#pragma unroll
    for (int co = 0; co < 10; co++) {
        float bb = bias[co0 + co];
#pragma unroll
        for (int p = 0; p < 4; p++) {
            int ly = 2 * ty + (p >> 1);
            int lx = 2 * tx + (p & 1);
            float v = acc[co][p] + bb;
            v = v > 0.f ? v : 0.f;
            out[(((size_t)b * F + co0 + co) * HW + tileY + ly) * HW + tileX + lx] = v;
        }
    }
}

// ---------------------------------------------------------------------------
// Fused: 1x1 conv (100 -> 441 logits) + softmax + 21x21 kernel apply.
// Block: 256 threads = 8 warps = 8 consecutive x-pixels at one (b, y).
// Online softmax per lane, merged across the warp at the end.
// ---------------------------------------------------------------------------
__global__ __launch_bounds__(256)
void kp_fused(const float* __restrict__ feat, const float* __restrict__ noisy,
              const float* __restrict__ w_kp, const float* __restrict__ b_kp,
              float* __restrict__ out) {
    __shared__ float s_feat[8][104];
    __shared__ float s_patch[3][21][28];
    __shared__ float s_w[64 * 101];   // 63-row weight chunk, pitch 101 (conflict-free)

    const int t = threadIdx.x;
    const int lane = t & 31, wid = t >> 5;
    const int x0 = blockIdx.x * 8;
    const int y = blockIdx.y;
    const int b = blockIdx.z;

    // features for the 8 pixels of this block
    for (int i = t; i < 8 * F; i += 256) {
        int pix = i & 7, f = i >> 3;
        s_feat[pix][f] = feat[(((size_t)b * F + f) * HW + y) * HW + x0 + pix];
    }
    // 21x28 noisy patch per channel (covers all 8 pixels' 21x21 windows)
    for (int i = t; i < 3 * 21 * 28; i += 256) {
        int c = i / (21 * 28);
        int rem = i - c * (21 * 28);
        int dy = rem / 28, dx = rem - dy * 28;
        int gy = y + dy - 10, gx = x0 + dx - 10;
        float v = 0.f;
        if ((unsigned)gy < HW && (unsigned)gx < HW)
            v = noisy[(((size_t)b * 3 + c) * HW + gy) * HW + gx];
        s_patch[c][dy][dx] = v;
    }

    float m = -1e30f, se = 0.f, o0 = 0.f, o1 = 0.f, o2 = 0.f;
    const int xl = wid;  // this warp's pixel offset inside the patch

    for (int ch = 0; ch < 7; ch++) {
        __syncthreads();
        const int j0 = ch * 63;
        for (int i = t; i < 63 * F; i += 256) {
            int jj = i / F, f = i - jj * F;
            s_w[jj * 101 + f] = w_kp[(size_t)(j0 + jj) * F + f];
        }
        __syncthreads();

        const int jj0 = lane;
        const int jj1 = lane + 32;
        float a0 = b_kp[j0 + jj0];
        float a1acc = 0.f;
        const float* w0 = s_w + jj0 * 101;
        const float* w1 = s_w + jj1 * 101;   // row 63 exists (garbage) but masked below
        const float* fv = s_feat[wid];
#pragma unroll 5
        for (int f = 0; f < F; f++) {
            float x = fv[f];
            a0 = fmaf(w0[f], x, a0);
            a1acc = fmaf(w1[f], x, a1acc);
        }

        // online-softmax update with a0 (always valid: j0+lane <= 378+31 < 441)
        {
            int j = j0 + jj0;
            int ky = j / 21, kx = j - ky * 21;
            float mn = fmaxf(m, a0);
            float sc = __expf(m - mn);
            float e = __expf(a0 - mn);
            m = mn;
            se = se * sc + e;
            o0 = o0 * sc + e * s_patch[0][ky][kx + xl];
            o1 = o1 * sc + e * s_patch[1][ky][kx + xl];
            o2 = o2 * sc + e * s_patch[2][ky][kx + xl];
        }
        if (jj1 < 63) {
            float a1 = b_kp[j0 + jj1] + a1acc;
            int j = j0 + jj1;
            int ky = j / 21, kx = j - ky * 21;
            float mn = fmaxf(m, a1);
            float sc = __expf(m - mn);
            float e = __expf(a1 - mn);
            m = mn;
            se = se * sc + e;
            o0 = o0 * sc + e * s_patch[0][ky][kx + xl];
            o1 = o1 * sc + e * s_patch[1][ky][kx + xl];
            o2 = o2 * sc + e * s_patch[2][ky][kx + xl];
        }
    }

    // merge per-lane online-softmax states across the warp
    float M = m;
#pragma unroll
    for (int o = 16; o; o >>= 1) M = fmaxf(M, __shfl_xor_sync(0xffffffffu, M, o));
    float fct = __expf(m - M);
    se *= fct; o0 *= fct; o1 *= fct; o2 *= fct;
#pragma unroll
    for (int o = 16; o; o >>= 1) {
        se += __shfl_xor_sync(0xffffffffu, se, o);
        o0 += __shfl_xor_sync(0xffffffffu, o0, o);
        o1 += __shfl_xor_sync(0xffffffffu, o1, o);
        o2 += __shfl_xor_sync(0xffffffffu, o2, o);
    }
    if (lane == 0) {
        float inv = 1.f / se;
        out[(((size_t)b * 3 + 0) * HW + y) * HW + x0 + wid] = o0 * inv;
        out[(((size_t)b * 3 + 1) * HW + y) * HW + x0 + wid] = o1 * inv;
        out[(((size_t)b * 3 + 2) * HW + y) * HW + x0 + wid] = o2 * inv;
    }
}

// ---------------------------------------------------------------------------
extern "C" void kernel_launch(void* const* d_in, const int* in_sizes, int n_in,
                              void* d_out, int out_size) {
    const float* noisy = (const float*)d_in[0];
    const float* w_in  = (const float*)d_in[1];
    const float* b_in  = (const float*)d_in[2];
    const float* w_hid = (const float*)d_in[3];
    const float* b_hid = (const float*)d_in[4];
    const float* w_kp  = (const float*)d_in[5];
    const float* b_kp  = (const float*)d_in[6];
    float* out = (float*)d_out;

    float *buf0, *buf1;
    cudaGetSymbolAddress((void**)&buf0, g_buf0);
    cudaGetSymbolAddress((void**)&buf1, g_buf1);

    dim3 grid(36, 10, 2), blk(256);

    conv5_relu<3, 3><<<grid, blk>>>(noisy, w_in, b_in, buf0);

    const float* src = buf0;
    float* dst = buf1;
    for (int l = 0; l < 7; l++) {
        conv5_relu<100, 4><<<grid, blk>>>(src, w_hid + (size_t)l * F * F * 25,
                                          b_hid + l * F, dst);
        float* tmp = (float*)src;
        src = dst;
        dst = tmp;
    }
    // after 7 swaps, src = buf1 holds the final activations
    kp_fused<<<dim3(24, 192, 2), blk>>>(src, noisy, w_kp, b_kp, out);
}

// round 3
// speedup vs baseline: 3.4303x; 3.4303x over previous
#include <cuda_runtime.h>
#include <cuda_fp16.h>
#include <cstdint>

#define HW 192
#define F 100
#define CP 112            // padded channel count (stored)
#define PITCH 120         // smem ci pitch in halves (240B -> conflict-free)

// Activation ping-pong buffers: fp16 NHWC[112]: 2*192*192*112 halves = 16.5 MB each.
__device__ __half g_act0[2 * HW * HW * CP];
__device__ __half g_act1[2 * HW * HW * CP];
// Transformed hidden weights: [layer7][tap25][co128][ci112] fp16 = 10 MB.
__device__ __half g_wt[7 * 25 * 128 * CP];

// ---------------------------------------------------------------------------
// PTX helpers
// ---------------------------------------------------------------------------
__device__ __forceinline__ uint32_t smem_u32(const void* p) {
    return (uint32_t)__cvta_generic_to_shared(p);
}
__device__ __forceinline__ void ldm_x4(uint32_t* r, uint32_t addr) {
    asm volatile("ldmatrix.sync.aligned.m8n8.x4.shared.b16 {%0,%1,%2,%3}, [%4];"
                 : "=r"(r[0]), "=r"(r[1]), "=r"(r[2]), "=r"(r[3]) : "r"(addr));
}
__device__ __forceinline__ void mma16816(float* c, const uint32_t* a, const uint32_t* b) {
    asm volatile(
        "mma.sync.aligned.m16n8k16.row.col.f32.f16.f16.f32 "
        "{%0,%1,%2,%3}, {%4,%5,%6,%7}, {%8,%9}, {%0,%1,%2,%3};"
        : "+f"(c[0]), "+f"(c[1]), "+f"(c[2]), "+f"(c[3])
        : "r"(a[0]), "r"(a[1]), "r"(a[2]), "r"(a[3]), "r"(b[0]), "r"(b[1]));
}

// ---------------------------------------------------------------------------
// Weight transform: g_wt[l][tap][co][ci] = w_hidden[l][co][ci][tap] (fp16, zero-pad)
// ---------------------------------------------------------------------------
__global__ void wt_transform(const float* __restrict__ w_hid) {
    int idx = blockIdx.x * 256 + threadIdx.x;
    if (idx >= 7 * 25 * 128 * CP) return;
    int ci = idx % CP;
    int co = (idx / CP) % 128;
    int tap = (idx / (CP * 128)) % 25;
    int l = idx / (CP * 128 * 25);
    float v = 0.f;
    if (co < F && ci < F)
        v = w_hid[(((size_t)l * F + co) * F + ci) * 25 + tap];
    g_wt[idx] = __float2half(v);
}

// ---------------------------------------------------------------------------
// Input conv 5x5 (3->100) + relu, fp32 FFMA, output fp16 NHWC[112].
// ---------------------------------------------------------------------------
__global__ __launch_bounds__(256)
void conv_in(const float* __restrict__ in, const float* __restrict__ w,
             const float* __restrict__ bias, __half* __restrict__ out) {
    __shared__ float s_in[3][36][37];
    __shared__ float s_w[3][25][10];

    const int t = threadIdx.x;
    const int tx = t & 15, ty = t >> 4;
    const int tileX = (blockIdx.x % 6) * 32;
    const int tileY = (blockIdx.x / 6) * 32;
    const int co0 = blockIdx.y * 10;
    const int b = blockIdx.z;
    const float* inb = in + (size_t)b * 3 * (HW * HW);

    for (int i = t; i < 3 * 36 * 36; i += 256) {
        int cc = i / (36 * 36);
        int rem = i - cc * (36 * 36);
        int r = rem / 36, c = rem - r * 36;
        int gy = tileY + r - 2, gx = tileX + c - 2;
        float v = 0.f;
        if ((unsigned)gy < HW && (unsigned)gx < HW)
            v = inb[(size_t)cc * (HW * HW) + gy * HW + gx];
        s_in[cc][r][c] = v;
    }
    for (int i = t; i < 3 * 250; i += 256) {
        int co = i % 10;
        int tap = (i / 10) % 25;
        int cc = i / 250;
        s_w[cc][tap][co] = w[((size_t)(co0 + co) * 3 + cc) * 25 + tap];
    }
    __syncthreads();

    float acc[10][4];
#pragma unroll
    for (int c = 0; c < 10; c++)
#pragma unroll
        for (int p = 0; p < 4; p++) acc[c][p] = 0.f;

#pragma unroll
    for (int cc = 0; cc < 3; cc++) {
#pragma unroll 1
        for (int ky = 0; ky < 5; ky++) {
            const int r0 = 2 * ty + ky;
#pragma unroll
            for (int kx = 0; kx < 5; kx++) {
                const int c0 = 2 * tx + kx;
                float x00 = s_in[cc][r0][c0];
                float x01 = s_in[cc][r0][c0 + 1];
                float x10 = s_in[cc][r0 + 1][c0];
                float x11 = s_in[cc][r0 + 1][c0 + 1];
                const int tap = ky * 5 + kx;
#pragma unroll
                for (int co = 0; co < 10; co++) {
                    float wv = s_w[cc][tap][co];
                    acc[co][0] = fmaf(wv, x00, acc[co][0]);
                    acc[co][1] = fmaf(wv, x01, acc[co][1]);
                    acc[co][2] = fmaf(wv, x10, acc[co][2]);
                    acc[co][3] = fmaf(wv, x11, acc[co][3]);
                }
            }
        }
    }

#pragma unroll
    for (int co = 0; co < 10; co++) {
        float bb = bias[co0 + co];
#pragma unroll
        for (int p = 0; p < 4; p++) {
            int ly = 2 * ty + (p >> 1);
            int lx = 2 * tx + (p & 1);
            float v = acc[co][p] + bb;
            v = v > 0.f ? v : 0.f;
            out[((size_t)(b * HW + tileY + ly) * HW + tileX + lx) * CP + co0 + co] =
                __float2half(v);
        }
    }
}

// ---------------------------------------------------------------------------
// Hidden conv 5x5 (100->100) + relu, fp16 tensor cores.
// CTA: 256 thr = 8 warps (4 M x 2 N). Tile: 128 couts x 128 pixels (16w x 8h).
// 25 shifted GEMMs (one per tap), K = 112 channels.
// ---------------------------------------------------------------------------
__global__ __launch_bounds__(256, 2)
void conv_hidden(const __half* __restrict__ act_in, const __half* __restrict__ wt,
                 const float* __restrict__ bias, __half* __restrict__ act_out) {
    extern __shared__ __half smem[];
    __half* s_patch = smem;                    // 12*20 pixel slots * PITCH halves
    __half* s_A = smem + 12 * 20 * PITCH;      // 128 rows * PITCH halves

    const int t = threadIdx.x;
    const int lane = t & 31, w = t >> 5;
    const int mw = w & 3, nw = w >> 2;
    const int g = lane >> 2, tg = lane & 3;
    const int tileX = (blockIdx.x % 12) * 16;
    const int tileY = (blockIdx.x / 12) * 8;
    const int b = blockIdx.z;
    const int co0 = mw * 32;

    // Stage input patch: 12x20 pixels, 112 channels each (zero at borders).
    {
        const __half* actb = act_in + (size_t)b * HW * HW * CP;
        for (int i = t; i < 12 * 20; i += 256) {
            int r = i / 20, c = i % 20;
            int gy = tileY + r - 2, gx = tileX + c - 2;
            uint4* dst = (uint4*)&s_patch[i * PITCH];
            if ((unsigned)gy < HW && (unsigned)gx < HW) {
                const uint4* src = (const uint4*)&actb[((size_t)gy * HW + gx) * CP];
#pragma unroll
                for (int j = 0; j < 14; j++) dst[j] = src[j];
            } else {
                uint4 z = make_uint4(0, 0, 0, 0);
#pragma unroll
                for (int j = 0; j < 14; j++) dst[j] = z;
            }
        }
    }

    float acc[2][8][4];
#pragma unroll
    for (int mi = 0; mi < 2; mi++)
#pragma unroll
        for (int ni = 0; ni < 8; ni++)
#pragma unroll
            for (int p = 0; p < 4; p++) acc[mi][ni][p] = 0.f;

    for (int tap = 0; tap < 25; tap++) {
        __syncthreads();
        // Stage per-tap A tile: 128 co x 112 ci.
        {
            const __half* wsrc = wt + (size_t)tap * 128 * CP;
            for (int i = t; i < 1792; i += 256) {
                int co = i / 14, j = i % 14;
                ((uint4*)&s_A[co * PITCH])[j] = ((const uint4*)&wsrc[co * CP])[j];
            }
        }
        __syncthreads();

        const int ky = tap / 5, kx = tap % 5;
        const int arow = (lane & 15);
        const int acol = (lane >> 4) * 8;

#pragma unroll 1
        for (int kc = 0; kc < CP; kc += 16) {
            uint32_t a[2][4];
#pragma unroll
            for (int mi = 0; mi < 2; mi++) {
                uint32_t addr = smem_u32(&s_A[(co0 + mi * 16 + arow) * PITCH + kc + acol]);
                ldm_x4(a[mi], addr);
            }
            uint32_t bf[8][2];
#pragma unroll
            for (int ni = 0; ni < 8; ni++) {
                int pr = nw * 4 + (ni >> 1) + ky;
                int pc = ((ni & 1) << 3) + g + kx;
                const __half* p = &s_patch[(pr * 20 + pc) * PITCH + kc + 2 * tg];
                bf[ni][0] = *(const uint32_t*)p;
                bf[ni][1] = *(const uint32_t*)(p + 8);
            }
#pragma unroll
            for (int mi = 0; mi < 2; mi++)
#pragma unroll
                for (int ni = 0; ni < 8; ni++)
                    mma16816(acc[mi][ni], a[mi], bf[ni]);
        }
    }

    // Writeback: bias + relu -> fp16 NHWC (co < 100 only; pad stays zero).
#pragma unroll
    for (int mi = 0; mi < 2; mi++) {
        int co_a = co0 + mi * 16 + g;
        int co_b = co_a + 8;
        float ba = (co_a < F) ? bias[co_a] : 0.f;
        float bb = (co_b < F) ? bias[co_b] : 0.f;
#pragma unroll
        for (int ni = 0; ni < 8; ni++) {
            int py = tileY + nw * 4 + (ni >> 1);
            int px = tileX + ((ni & 1) << 3) + 2 * tg;
            size_t base = ((size_t)(b * HW + py) * HW + px) * CP;
            if (co_a < F) {
                float v0 = acc[mi][ni][0] + ba; v0 = v0 > 0.f ? v0 : 0.f;
                float v1 = acc[mi][ni][1] + ba; v1 = v1 > 0.f ? v1 : 0.f;
                act_out[base + co_a] = __float2half(v0);
                act_out[base + CP + co_a] = __float2half(v1);
            }
            if (co_b < F) {
                float v2 = acc[mi][ni][2] + bb; v2 = v2 > 0.f ? v2 : 0.f;
                float v3 = acc[mi][ni][3] + bb; v3 = v3 > 0.f ? v3 : 0.f;
                act_out[base + co_b] = __float2half(v2);
                act_out[base + CP + co_b] = __float2half(v3);
            }
        }
    }
}

// ---------------------------------------------------------------------------
// Fused: 1x1 conv (100 -> 441 logits) + softmax + 21x21 kernel apply.
// feat: fp16 NHWC[112]. Rest fp32, same as round-1.
// ---------------------------------------------------------------------------
__global__ __launch_bounds__(256)
void kp_fused(const __half* __restrict__ feat, const float* __restrict__ noisy,
              const float* __restrict__ w_kp, const float* __restrict__ b_kp,
              float* __restrict__ out) {
    __shared__ float s_feat[8][CP];
    __shared__ float s_patch[3][21][28];
    __shared__ float s_w[64 * 101];

    const int t = threadIdx.x;
    const int lane = t & 31, wid = t >> 5;
    const int x0 = blockIdx.x * 8;
    const int y = blockIdx.y;
    const int b = blockIdx.z;

    for (int i = t; i < 8 * CP; i += 256) {
        int pix = i / CP, f = i % CP;
        s_feat[pix][f] =
            __half2float(feat[((size_t)(b * HW + y) * HW + x0 + pix) * CP + f]);
    }
    for (int i = t; i < 3 * 21 * 28; i += 256) {
        int c = i / (21 * 28);
        int rem = i - c * (21 * 28);
        int dy = rem / 28, dx = rem - dy * 28;
        int gy = y + dy - 10, gx = x0 + dx - 10;
        float v = 0.f;
        if ((unsigned)gy < HW && (unsigned)gx < HW)
            v = noisy[(((size_t)b * 3 + c) * HW + gy) * HW + gx];
        s_patch[c][dy][dx] = v;
    }

    float m = -1e30f, se = 0.f, o0 = 0.f, o1 = 0.f, o2 = 0.f;
    const int xl = wid;

    for (int ch = 0; ch < 7; ch++) {
        __syncthreads();
        const int j0 = ch * 63;
        for (int i = t; i < 63 * F; i += 256) {
            int jj = i / F, f = i - jj * F;
            s_w[jj * 101 + f] = w_kp[(size_t)(j0 + jj) * F + f];
        }
        __syncthreads();

        const int jj0 = lane;
        const int jj1 = lane + 32;
        float a0 = b_kp[j0 + jj0];
        float a1acc = 0.f;
        const float* w0 = s_w + jj0 * 101;
        const float* w1 = s_w + jj1 * 101;
        const float* fv = s_feat[wid];
#pragma unroll 5
        for (int f = 0; f < F; f++) {
            float x = fv[f];
            a0 = fmaf(w0[f], x, a0);
            a1acc = fmaf(w1[f], x, a1acc);
        }
        {
            int j = j0 + jj0;
            int ky = j / 21, kx = j - ky * 21;
            float mn = fmaxf(m, a0);
            float sc = __expf(m - mn);
            float e = __expf(a0 - mn);
            m = mn;
            se = se * sc + e;
            o0 = o0 * sc + e * s_patch[0][ky][kx + xl];
            o1 = o1 * sc + e * s_patch[1][ky][kx + xl];
            o2 = o2 * sc + e * s_patch[2][ky][kx + xl];
        }
        if (jj1 < 63) {
            float a1 = b_kp[j0 + jj1] + a1acc;
            int j = j0 + jj1;
            int ky = j / 21, kx = j - ky * 21;
            float mn = fmaxf(m, a1);
            float sc = __expf(m - mn);
            float e = __expf(a1 - mn);
            m = mn;
            se = se * sc + e;
            o0 = o0 * sc + e * s_patch[0][ky][kx + xl];
            o1 = o1 * sc + e * s_patch[1][ky][kx + xl];
            o2 = o2 * sc + e * s_patch[2][ky][kx + xl];
        }
    }

    float M = m;
#pragma unroll
    for (int o = 16; o; o >>= 1) M = fmaxf(M, __shfl_xor_sync(0xffffffffu, M, o));
    float fct = __expf(m - M);
    se *= fct; o0 *= fct; o1 *= fct; o2 *= fct;
#pragma unroll
    for (int o = 16; o; o >>= 1) {
        se += __shfl_xor_sync(0xffffffffu, se, o);
        o0 += __shfl_xor_sync(0xffffffffu, o0, o);
        o1 += __shfl_xor_sync(0xffffffffu, o1, o);
        o2 += __shfl_xor_sync(0xffffffffu, o2, o);
    }
    if (lane == 0) {
        float inv = 1.f / se;
        out[(((size_t)b * 3 + 0) * HW + y) * HW + x0 + wid] = o0 * inv;
        out[(((size_t)b * 3 + 1) * HW + y) * HW + x0 + wid] = o1 * inv;
        out[(((size_t)b * 3 + 2) * HW + y) * HW + x0 + wid] = o2 * inv;
    }
}

// ---------------------------------------------------------------------------
extern "C" void kernel_launch(void* const* d_in, const int* in_sizes, int n_in,
                              void* d_out, int out_size) {
    const float* noisy = (const float*)d_in[0];
    const float* w_in  = (const float*)d_in[1];
    const float* b_in  = (const float*)d_in[2];
    const float* w_hid = (const float*)d_in[3];
    const float* b_hid = (const float*)d_in[4];
    const float* w_kp  = (const float*)d_in[5];
    const float* b_kp  = (const float*)d_in[6];
    float* out = (float*)d_out;

    __half *act0, *act1, *wt;
    cudaGetSymbolAddress((void**)&act0, g_act0);
    cudaGetSymbolAddress((void**)&act1, g_act1);
    cudaGetSymbolAddress((void**)&wt, g_wt);

    const int smem_hidden = 12 * 20 * PITCH * 2 + 128 * PITCH * 2;  // 88320 B
    cudaFuncSetAttribute(conv_hidden, cudaFuncAttributeMaxDynamicSharedMemorySize,
                         smem_hidden);

    const size_t actBytes = (size_t)2 * HW * HW * CP * sizeof(__half);
    cudaMemsetAsync(act0, 0, actBytes);
    cudaMemsetAsync(act1, 0, actBytes);

    wt_transform<<<(7 * 25 * 128 * CP + 255) / 256, 256>>>(w_hid);

    conv_in<<<dim3(36, 10, 2), 256>>>(noisy, w_in, b_in, act0);

    const __half* src = act0;
    __half* dst = act1;
    for (int l = 0; l < 7; l++) {
        conv_hidden<<<dim3(288, 1, 2), 256, smem_hidden>>>(
            src, wt + (size_t)l * 25 * 128 * CP, b_hid + l * F, dst);
        __half* tmp = (__half*)src;
        src = dst;
        dst = tmp;
    }
    // after 7 layers, src = act1 holds final features
    kp_fused<<<dim3(24, HW, 2), 256>>>(src, noisy, w_kp, b_kp, out);
}

// round 6
// speedup vs baseline: 5.1279x; 1.4949x over previous
#include <cuda_runtime.h>
#include <cuda_fp16.h>
#include <cstdint>

#define HW 192
#define F 100
#define CP 112            // padded channel count (stored)
#define PITCH 120         // smem ci pitch in halves (240B -> conflict-free)
#define KK 441
#define KKP 448           // padded logit count

// Activation ping-pong buffers: fp16 NHWC[112]: 2*192*192*112 halves = 16.5 MB each.
__device__ __half g_act0[2 * HW * HW * CP];
__device__ __half g_act1[2 * HW * HW * CP];
// Transformed hidden weights: [layer7][tap25][co128][ci112] fp16 = 10 MB.
__device__ __half g_wt[7 * 25 * 128 * CP];
// Transformed kp weights: [448][112] fp16.
__device__ __half g_wkp[KKP * CP];
// Logits: [b][y][x][448] fp16 = 66 MB.
__device__ __half g_logits[2 * HW * HW * KKP];

// ---------------------------------------------------------------------------
// PTX helpers
// ---------------------------------------------------------------------------
__device__ __forceinline__ uint32_t smem_u32(const void* p) {
    return (uint32_t)__cvta_generic_to_shared(p);
}
__device__ __forceinline__ void ldm_x4(uint32_t* r, uint32_t addr) {
    asm volatile("ldmatrix.sync.aligned.m8n8.x4.shared.b16 {%0,%1,%2,%3}, [%4];"
                 : "=r"(r[0]), "=r"(r[1]), "=r"(r[2]), "=r"(r[3]) : "r"(addr));
}
__device__ __forceinline__ void mma16816(float* c, const uint32_t* a, const uint32_t* b) {
    asm volatile(
        "mma.sync.aligned.m16n8k16.row.col.f32.f16.f16.f32 "
        "{%0,%1,%2,%3}, {%4,%5,%6,%7}, {%8,%9}, {%0,%1,%2,%3};"
        : "+f"(c[0]), "+f"(c[1]), "+f"(c[2]), "+f"(c[3])
        : "r"(a[0]), "r"(a[1]), "r"(a[2]), "r"(a[3]), "r"(b[0]), "r"(b[1]));
}

// ---------------------------------------------------------------------------
// Weight transforms
// ---------------------------------------------------------------------------
__global__ void wt_transform(const float* __restrict__ w_hid) {
    int idx = blockIdx.x * 256 + threadIdx.x;
    if (idx >= 7 * 25 * 128 * CP) return;
    int ci = idx % CP;
    int co = (idx / CP) % 128;
    int tap = (idx / (CP * 128)) % 25;
    int l = idx / (CP * 128 * 25);
    float v = 0.f;
    if (co < F && ci < F)
        v = w_hid[(((size_t)l * F + co) * F + ci) * 25 + tap];
    g_wt[idx] = __float2half(v);
}

__global__ void wkp_transform(const float* __restrict__ w_kp) {
    int idx = blockIdx.x * 256 + threadIdx.x;
    if (idx >= KKP * CP) return;
    int ci = idx % CP;
    int co = idx / CP;
    float v = 0.f;
    if (co < KK && ci < F) v = w_kp[(size_t)co * F + ci];
    g_wkp[idx] = __float2half(v);
}

// ---------------------------------------------------------------------------
// Input conv 5x5 (3->100) + relu, fp32 FFMA, output fp16 NHWC[112].
// ---------------------------------------------------------------------------
__global__ __launch_bounds__(256)
void conv_in(const float* __restrict__ in, const float* __restrict__ w,
             const float* __restrict__ bias, __half* __restrict__ out) {
    __shared__ float s_in[3][36][37];
    __shared__ float s_w[3][25][10];

    const int t = threadIdx.x;
    const int tx = t & 15, ty = t >> 4;
    const int tileX = (blockIdx.x % 6) * 32;
    const int tileY = (blockIdx.x / 6) * 32;
    const int co0 = blockIdx.y * 10;
    const int b = blockIdx.z;
    const float* inb = in + (size_t)b * 3 * (HW * HW);

    for (int i = t; i < 3 * 36 * 36; i += 256) {
        int cc = i / (36 * 36);
        int rem = i - cc * (36 * 36);
        int r = rem / 36, c = rem - r * 36;
        int gy = tileY + r - 2, gx = tileX + c - 2;
        float v = 0.f;
        if ((unsigned)gy < HW && (unsigned)gx < HW)
            v = inb[(size_t)cc * (HW * HW) + gy * HW + gx];
        s_in[cc][r][c] = v;
    }
    for (int i = t; i < 3 * 250; i += 256) {
        int co = i % 10;
        int tap = (i / 10) % 25;
        int cc = i / 250;
        s_w[cc][tap][co] = w[((size_t)(co0 + co) * 3 + cc) * 25 + tap];
    }
    __syncthreads();

    float acc[10][4];
#pragma unroll
    for (int c = 0; c < 10; c++)
#pragma unroll
        for (int p = 0; p < 4; p++) acc[c][p] = 0.f;

#pragma unroll
    for (int cc = 0; cc < 3; cc++) {
#pragma unroll 1
        for (int ky = 0; ky < 5; ky++) {
            const int r0 = 2 * ty + ky;
#pragma unroll
            for (int kx = 0; kx < 5; kx++) {
                const int c0 = 2 * tx + kx;
                float x00 = s_in[cc][r0][c0];
                float x01 = s_in[cc][r0][c0 + 1];
                float x10 = s_in[cc][r0 + 1][c0];
                float x11 = s_in[cc][r0 + 1][c0 + 1];
                const int tap = ky * 5 + kx;
#pragma unroll
                for (int co = 0; co < 10; co++) {
                    float wv = s_w[cc][tap][co];
                    acc[co][0] = fmaf(wv, x00, acc[co][0]);
                    acc[co][1] = fmaf(wv, x01, acc[co][1]);
                    acc[co][2] = fmaf(wv, x10, acc[co][2]);
                    acc[co][3] = fmaf(wv, x11, acc[co][3]);
                }
            }
        }
    }

#pragma unroll
    for (int co = 0; co < 10; co++) {
        float bb = bias[co0 + co];
#pragma unroll
        for (int p = 0; p < 4; p++) {
            int ly = 2 * ty + (p >> 1);
            int lx = 2 * tx + (p & 1);
            float v = acc[co][p] + bb;
            v = v > 0.f ? v : 0.f;
            out[((size_t)(b * HW + tileY + ly) * HW + tileX + lx) * CP + co0 + co] =
                __float2half(v);
        }
    }
}

// ---------------------------------------------------------------------------
// Hidden conv 5x5 (100->100) + relu, fp16 tensor cores.
// CTA: 256 thr = 8 warps (4 M x 2 N). Tile: 128 couts x 128 pixels (16w x 8h).
// 25 shifted GEMMs (one per tap), K = 112 channels. All frags via ldmatrix.
// ---------------------------------------------------------------------------
__global__ __launch_bounds__(256, 2)
void conv_hidden(const __half* __restrict__ act_in, const __half* __restrict__ wt,
                 const float* __restrict__ bias, __half* __restrict__ act_out) {
    extern __shared__ __half smem[];
    __half* s_patch = smem;                    // 12*20 pixel slots * PITCH halves
    __half* s_A = smem + 12 * 20 * PITCH;      // 128 rows * PITCH halves

    const int t = threadIdx.x;
    const int lane = t & 31, w = t >> 5;
    const int mw = w & 3, nw = w >> 2;
    const int g = lane >> 2, tg = lane & 3;
    const int tileX = (blockIdx.x % 12) * 16;
    const int tileY = (blockIdx.x / 12) * 8;
    const int b = blockIdx.z;
    const int co0 = mw * 32;

    // Stage input patch: 12x20 pixels, 112 channels each. Coalesced: i%14 inner.
    {
        const __half* actb = act_in + (size_t)b * HW * HW * CP;
        for (int i = t; i < 12 * 20 * 14; i += 256) {
            int pix = i / 14, j = i % 14;
            int r = pix / 20, c = pix % 20;
            int gy = tileY + r - 2, gx = tileX + c - 2;
            uint4 v = make_uint4(0, 0, 0, 0);
            if ((unsigned)gy < HW && (unsigned)gx < HW)
                v = ((const uint4*)&actb[((size_t)gy * HW + gx) * CP])[j];
            ((uint4*)&s_patch[pix * PITCH])[j] = v;
        }
    }

    // Precompute ldmatrix base addresses.
    uint32_t a_base[2];
#pragma unroll
    for (int mi = 0; mi < 2; mi++)
        a_base[mi] = smem_u32(&s_A[(co0 + mi * 16 + (lane & 15)) * PITCH + (lane >> 4) * 8]);

    uint32_t b_base[4];
    {
        int sub = lane >> 3, pix = lane & 7;
#pragma unroll
        for (int j = 0; j < 4; j++) {
            int ni = 2 * j + (sub >> 1);
            int khalf = sub & 1;
            int pr0 = nw * 4 + (ni >> 1);
            int pc0 = (ni & 1) * 8 + pix;
            b_base[j] = smem_u32(&s_patch[(pr0 * 20 + pc0) * PITCH + khalf * 8]);
        }
    }

    float acc[2][8][4];
#pragma unroll
    for (int mi = 0; mi < 2; mi++)
#pragma unroll
        for (int ni = 0; ni < 8; ni++)
#pragma unroll
            for (int p = 0; p < 4; p++) acc[mi][ni][p] = 0.f;

#pragma unroll 1
    for (int tap = 0; tap < 25; tap++) {
        __syncthreads();
        // Stage per-tap A tile: 128 co x 112 ci.
        {
            const __half* wsrc = wt + (size_t)tap * 128 * CP;
            for (int i = t; i < 1792; i += 256) {
                int co = i / 14, j = i % 14;
                ((uint4*)&s_A[co * PITCH])[j] = ((const uint4*)&wsrc[co * CP])[j];
            }
        }
        __syncthreads();

        const int ky = tap / 5, kx = tap % 5;
        const uint32_t tapoff = (uint32_t)(ky * 20 + kx) * PITCH * 2;

#pragma unroll
        for (int kc = 0; kc < CP; kc += 16) {
            uint32_t a[2][4];
#pragma unroll
            for (int mi = 0; mi < 2; mi++) ldm_x4(a[mi], a_base[mi] + kc * 2);
            uint32_t bf[8][2];
#pragma unroll
            for (int j = 0; j < 4; j++) {
                uint32_t r[4];
                ldm_x4(r, b_base[j] + tapoff + kc * 2);
                bf[2 * j][0] = r[0]; bf[2 * j][1] = r[1];
                bf[2 * j + 1][0] = r[2]; bf[2 * j + 1][1] = r[3];
            }
#pragma unroll
            for (int mi = 0; mi < 2; mi++)
#pragma unroll
                for (int ni = 0; ni < 8; ni++)
                    mma16816(acc[mi][ni], a[mi], bf[ni]);
        }
    }

    // Writeback: bias + relu -> fp16 NHWC (co < 100 only; pad stays zero).
#pragma unroll
    for (int mi = 0; mi < 2; mi++) {
        int co_a = co0 + mi * 16 + g;
        int co_b = co_a + 8;
        float ba = (co_a < F) ? bias[co_a] : 0.f;
        float bb = (co_b < F) ? bias[co_b] : 0.f;
#pragma unroll
        for (int ni = 0; ni < 8; ni++) {
            int py = tileY + nw * 4 + (ni >> 1);
            int px = tileX + ((ni & 1) << 3) + 2 * tg;
            size_t base = ((size_t)(b * HW + py) * HW + px) * CP;
            if (co_a < F) {
                float v0 = acc[mi][ni][0] + ba; v0 = v0 > 0.f ? v0 : 0.f;
                float v1 = acc[mi][ni][1] + ba; v1 = v1 > 0.f ? v1 : 0.f;
                act_out[base + co_a] = __float2half(v0);
                act_out[base + CP + co_a] = __float2half(v1);
            }
            if (co_b < F) {
                float v2 = acc[mi][ni][2] + bb; v2 = v2 > 0.f ? v2 : 0.f;
                float v3 = acc[mi][ni][3] + bb; v3 = v3 > 0.f ? v3 : 0.f;
                act_out[base + co_b] = __float2half(v2);
                act_out[base + CP + co_b] = __float2half(v3);
            }
        }
    }
}

// ---------------------------------------------------------------------------
// kp GEMM: logits[px][448] = wkp[448][112] x feat[px][112], fp16 tensor cores.
// Tile: 128 logit rows x 128 pixels (16w x 8h), no halo, single "tap".
// ---------------------------------------------------------------------------
__global__ __launch_bounds__(256, 2)
void kp_gemm(const __half* __restrict__ feat, const __half* __restrict__ wkp,
             const float* __restrict__ b_kp, __half* __restrict__ logits) {
    extern __shared__ __half smem[];
    __half* s_px = smem;                  // 128 * PITCH
    __half* s_A = smem + 128 * PITCH;     // 128 * PITCH

    const int t = threadIdx.x;
    const int lane = t & 31, w = t >> 5;
    const int mw = w & 3, nw = w >> 2;
    const int g = lane >> 2, tg = lane & 3;
    const int tileX = (blockIdx.x % 12) * 16;
    const int tileY = (blockIdx.x / 12) * 8;
    const int co0g = blockIdx.y * 128;
    const int b = blockIdx.z;
    const int co0 = mw * 32;

    {
        const __half* fb = feat + (size_t)b * HW * HW * CP;
        for (int i = t; i < 128 * 14; i += 256) {
            int pix = i / 14, j = i % 14;
            int gy = tileY + pix / 16, gx = tileX + (pix & 15);
            ((uint4*)&s_px[pix * PITCH])[j] =
                ((const uint4*)&fb[((size_t)gy * HW + gx) * CP])[j];
        }
        for (int i = t; i < 128 * 14; i += 256) {
            int co = i / 14, j = i % 14;
            uint4 v = make_uint4(0, 0, 0, 0);
            if (co0g + co < KKP)
                v = ((const uint4*)&wkp[(size_t)(co0g + co) * CP])[j];
            ((uint4*)&s_A[co * PITCH])[j] = v;
        }
    }
    __syncthreads();

    uint32_t a_base[2];
#pragma unroll
    for (int mi = 0; mi < 2; mi++)
        a_base[mi] = smem_u32(&s_A[(co0 + mi * 16 + (lane & 15)) * PITCH + (lane >> 4) * 8]);
    uint32_t b_base[4];
    {
        int sub = lane >> 3, pix = lane & 7;
#pragma unroll
        for (int j = 0; j < 4; j++) {
            int ni = 2 * j + (sub >> 1);
            int khalf = sub & 1;
            int pr0 = nw * 4 + (ni >> 1);
            int pc0 = (ni & 1) * 8 + pix;
            b_base[j] = smem_u32(&s_px[(pr0 * 16 + pc0) * PITCH + khalf * 8]);
        }
    }

    float acc[2][8][4];
#pragma unroll
    for (int mi = 0; mi < 2; mi++)
#pragma unroll
        for (int ni = 0; ni < 8; ni++)
#pragma unroll
            for (int p = 0; p < 4; p++) acc[mi][ni][p] = 0.f;

#pragma unroll
    for (int kc = 0; kc < CP; kc += 16) {
        uint32_t a[2][4];
#pragma unroll
        for (int mi = 0; mi < 2; mi++) ldm_x4(a[mi], a_base[mi] + kc * 2);
        uint32_t bf[8][2];
#pragma unroll
        for (int j = 0; j < 4; j++) {
            uint32_t r[4];
            ldm_x4(r, b_base[j] + kc * 2);
            bf[2 * j][0] = r[0]; bf[2 * j][1] = r[1];
            bf[2 * j + 1][0] = r[2]; bf[2 * j + 1][1] = r[3];
        }
#pragma unroll
        for (int mi = 0; mi < 2; mi++)
#pragma unroll
            for (int ni = 0; ni < 8; ni++)
                mma16816(acc[mi][ni], a[mi], bf[ni]);
    }

#pragma unroll
    for (int mi = 0; mi < 2; mi++) {
        int co_a = co0g + co0 + mi * 16 + g;
        int co_b = co_a + 8;
        float ba = (co_a < KK) ? b_kp[co_a] : 0.f;
        float bb = (co_b < KK) ? b_kp[co_b] : 0.f;
#pragma unroll
        for (int ni = 0; ni < 8; ni++) {
            int py = tileY + nw * 4 + (ni >> 1);
            int px = tileX + ((ni & 1) << 3) + 2 * tg;
            size_t base = ((size_t)(b * HW + py) * HW + px) * KKP;
            if (co_a < KK) {
                logits[base + co_a] = __float2half(acc[mi][ni][0] + ba);
                logits[base + KKP + co_a] = __float2half(acc[mi][ni][1] + ba);
            }
            if (co_b < KK) {
                logits[base + co_b] = __float2half(acc[mi][ni][2] + bb);
                logits[base + KKP + co_b] = __float2half(acc[mi][ni][3] + bb);
            }
        }
    }
}

// ---------------------------------------------------------------------------
// Softmax + 21x21 kernel apply. Warp per pixel, 8 pixels per block (one x-run).
// ---------------------------------------------------------------------------
__global__ __launch_bounds__(256)
void kp_apply(const __half* __restrict__ logits, const float* __restrict__ noisy,
              float* __restrict__ out) {
    __shared__ float s_patch[3][21][28];

    const int t = threadIdx.x;
    const int lane = t & 31, wid = t >> 5;
    const int x0 = blockIdx.x * 8;
    const int y = blockIdx.y;
    const int b = blockIdx.z;

    for (int i = t; i < 3 * 21 * 28; i += 256) {
        int c = i / (21 * 28);
        int rem = i - c * (21 * 28);
        int dy = rem / 28, dx = rem - dy * 28;
        int gy = y + dy - 10, gx = x0 + dx - 10;
        float v = 0.f;
        if ((unsigned)gy < HW && (unsigned)gx < HW)
            v = noisy[(((size_t)b * 3 + c) * HW + gy) * HW + gx];
        s_patch[c][dy][dx] = v;
    }
    __syncthreads();

    const __half* lp = logits + ((size_t)(b * HW + y) * HW + x0 + wid) * KKP;
    float L[14];
#pragma unroll
    for (int i = 0; i < 14; i++) {
        int j = i * 32 + lane;
        L[i] = (j < KK) ? __half2float(lp[j]) : -1e30f;
    }
    float m = -1e30f;
#pragma unroll
    for (int i = 0; i < 14; i++) m = fmaxf(m, L[i]);
#pragma unroll
    for (int o = 16; o; o >>= 1) m = fmaxf(m, __shfl_xor_sync(0xffffffffu, m, o));

    float se = 0.f, o0 = 0.f, o1 = 0.f, o2 = 0.f;
#pragma unroll
    for (int i = 0; i < 14; i++) {
        int j = i * 32 + lane;
        if (j < KK) {
            float e = __expf(L[i] - m);
            int ky = j / 21, kx = j - ky * 21;
            se += e;
            o0 += e * s_patch[0][ky][kx + wid];
            o1 += e * s_patch[1][ky][kx + wid];
            o2 += e * s_patch[2][ky][kx + wid];
        }
    }
#pragma unroll
    for (int o = 16; o; o >>= 1) {
        se += __shfl_xor_sync(0xffffffffu, se, o);
        o0 += __shfl_xor_sync(0xffffffffu, o0, o);
        o1 += __shfl_xor_sync(0xffffffffu, o1, o);
        o2 += __shfl_xor_sync(0xffffffffu, o2, o);
    }
    if (lane == 0) {
        float inv = 1.f / se;
        out[(((size_t)b * 3 + 0) * HW + y) * HW + x0 + wid] = o0 * inv;
        out[(((size_t)b * 3 + 1) * HW + y) * HW + x0 + wid] = o1 * inv;
        out[(((size_t)b * 3 + 2) * HW + y) * HW + x0 + wid] = o2 * inv;
    }
}

// ---------------------------------------------------------------------------
extern "C" void kernel_launch(void* const* d_in, const int* in_sizes, int n_in,
                              void* d_out, int out_size) {
    const float* noisy = (const float*)d_in[0];
    const float* w_in  = (const float*)d_in[1];
    const float* b_in  = (const float*)d_in[2];
    const float* w_hid = (const float*)d_in[3];
    const float* b_hid = (const float*)d_in[4];
    const float* w_kp  = (const float*)d_in[5];
    const float* b_kp  = (const float*)d_in[6];
    float* out = (float*)d_out;

    __half *act0, *act1, *wt, *wkp, *logits;
    cudaGetSymbolAddress((void**)&act0, g_act0);
    cudaGetSymbolAddress((void**)&act1, g_act1);
    cudaGetSymbolAddress((void**)&wt, g_wt);
    cudaGetSymbolAddress((void**)&wkp, g_wkp);
    cudaGetSymbolAddress((void**)&logits, g_logits);

    const int smem_hidden = 12 * 20 * PITCH * 2 + 128 * PITCH * 2;  // 88320 B
    const int smem_kp = 2 * 128 * PITCH * 2;                        // 61440 B
    cudaFuncSetAttribute(conv_hidden, cudaFuncAttributeMaxDynamicSharedMemorySize,
                         smem_hidden);
    cudaFuncSetAttribute(kp_gemm, cudaFuncAttributeMaxDynamicSharedMemorySize,
                         smem_kp);

    const size_t actBytes = (size_t)2 * HW * HW * CP * sizeof(__half);
    cudaMemsetAsync(act0, 0, actBytes);
    cudaMemsetAsync(act1, 0, actBytes);

    wt_transform<<<(7 * 25 * 128 * CP + 255) / 256, 256>>>(w_hid);
    wkp_transform<<<(KKP * CP + 255) / 256, 256>>>(w_kp);

    conv_in<<<dim3(36, 10, 2), 256>>>(noisy, w_in, b_in, act0);

    const __half* src = act0;
    __half* dst = act1;
    for (int l = 0; l < 7; l++) {
        conv_hidden<<<dim3(288, 1, 2), 256, smem_hidden>>>(
            src, wt + (size_t)l * 25 * 128 * CP, b_hid + l * F, dst);
        __half* tmp = (__half*)src;
        src = dst;
        dst = tmp;
    }

    kp_gemm<<<dim3(288, 4, 2), 256, smem_kp>>>(src, wkp, b_kp, logits);
    kp_apply<<<dim3(24, HW, 2), 256>>>(logits, noisy, out);
}